// round 1
// baseline (speedup 1.0000x reference)
#include <cuda_runtime.h>
#include <math.h>

static constexpr int B = 8, C = 256, E = 64, N = 4096;

// Scratch (device globals: allocation-free rule)
__device__ float g_fT[B * N * E];  // keys   [b][n][e]
__device__ float g_gT[B * N * E];  // queries
__device__ float g_hT[B * N * E];  // values
__device__ float g_vT[B * N * E];  // attention output

// ---------------------------------------------------------------------------
// Projection: f/g/hv = (W * x) * (1/sqrt(C)) + b, written transposed [b][n][e]
// grid: B * N/16 blocks, 256 threads
// ---------------------------------------------------------------------------
__global__ __launch_bounds__(256) void proj_kernel(
    const float* __restrict__ x,
    const float* __restrict__ wk, const float* __restrict__ bk,
    const float* __restrict__ wq, const float* __restrict__ bq,
    const float* __restrict__ wv, const float* __restrict__ bv)
{
    __shared__ float xs[16][260];    // [col][c], pad 260 (mult of 4, !=0 mod 32)
    __shared__ float outs[192][17];  // [row 0..191][col]

    int blk = blockIdx.x;
    int b   = blk >> 8;              // 256 col-tiles per batch
    int n0  = (blk & 255) << 4;
    const float* xb = x + ((size_t)b * C) * N;

    for (int idx = threadIdx.x; idx < 256 * 16; idx += 256) {
        int c = idx >> 4, col = idx & 15;
        xs[col][c] = xb[(size_t)c * N + n0 + col];
    }
    __syncthreads();

    int tx = threadIdx.x & 15;       // column
    int ty = threadIdx.x >> 4;       // 0..15
    const float4* x4 = (const float4*)&xs[tx][0];

    #pragma unroll
    for (int j = 0; j < 12; j++) {
        int r = ty + 16 * j;         // 0..191
        int e = r & 63;
        const float* w; float bias;
        if (r < 64)       { w = wk + e * C; bias = bk[e]; }
        else if (r < 128) { w = wq + e * C; bias = bq[e]; }
        else              { w = wv + e * C; bias = bv[e]; }
        const float4* w4 = (const float4*)w;
        float acc = 0.f;
        #pragma unroll 8
        for (int c4 = 0; c4 < 64; c4++) {
            float4 wv4 = w4[c4];
            float4 xv4 = x4[c4];
            acc += wv4.x * xv4.x + wv4.y * xv4.y + wv4.z * xv4.z + wv4.w * xv4.w;
        }
        outs[r][tx] = acc * 0.0625f + bias;  // 1/sqrt(256)
    }
    __syncthreads();

    for (int idx = threadIdx.x; idx < 16 * 64; idx += 256) {
        int nl = idx >> 6, e = idx & 63;
        size_t o = ((size_t)b * N + n0 + nl) * E + e;
        g_fT[o] = outs[e][nl];
        g_gT[o] = outs[64 + e][nl];
        g_hT[o] = outs[128 + e][nl];
    }
}

// ---------------------------------------------------------------------------
// Flash attention: 64-query tiles, online softmax over keys.
// All smem tiles 64x64 fp32, stored row-major with float4 XOR swizzle:
//   phys float4 slot = s ^ (row & 15)  -> conflict-free strided & broadcast reads
// Thread layout: qg = tid/16 (q group of 4), kg = tid%16 (k/e group of 4).
// grid: (N/64, B), 256 threads, 64 KB dynamic smem
// ---------------------------------------------------------------------------
__global__ __launch_bounds__(256) void flash_kernel()
{
    extern __shared__ float4 sm4[];
    float4* Ks4 = sm4;               // [64][16] swizzled
    float4* Qs4 = sm4 + 1024;
    float4* Vs4 = sm4 + 2048;
    float4* Ps4 = sm4 + 3072;
    __shared__ float m_s[64], l_s[64], alpha_s[64];

    int b  = blockIdx.y;
    int q0 = blockIdx.x << 6;
    int tid = threadIdx.x;
    int qg = tid >> 4, kg = tid & 15;

    const float4* Qg4 = (const float4*)(g_gT + ((size_t)b * N + q0) * E);
    for (int idx = tid; idx < 1024; idx += 256) {
        int row = idx >> 4, s = idx & 15;
        Qs4[(row << 4) | (s ^ (row & 15))] = Qg4[idx];
    }
    if (tid < 64) { m_s[tid] = -1e30f; l_s[tid] = 0.f; }
    __syncthreads();

    float Oa[4][4];                  // [e][q]
    #pragma unroll
    for (int i = 0; i < 4; i++)
        #pragma unroll
        for (int j = 0; j < 4; j++) Oa[i][j] = 0.f;

    const float4* Kb4 = (const float4*)(g_fT + (size_t)b * N * E);
    const float4* Vb4 = (const float4*)(g_hT + (size_t)b * N * E);

    for (int k0 = 0; k0 < N; k0 += 64) {
        const float4* Kg4 = Kb4 + ((size_t)k0 << 4);
        const float4* Vg4 = Vb4 + ((size_t)k0 << 4);
        for (int idx = tid; idx < 1024; idx += 256) {
            int row = idx >> 4, s = idx & 15;
            int sw = (row << 4) | (s ^ (row & 15));
            Ks4[sw] = Kg4[idx];
            Vs4[sw] = Vg4[idx];
        }
        __syncthreads();

        // S[k][q] = sum_e K[k][e] * Q[q][e]
        float S[4][4];
        #pragma unroll
        for (int i = 0; i < 4; i++)
            #pragma unroll
            for (int j = 0; j < 4; j++) S[i][j] = 0.f;

        #pragma unroll 4
        for (int e4 = 0; e4 < 16; e4++) {
            float4 qf[4], kf[4];
            #pragma unroll
            for (int j = 0; j < 4; j++) {
                int r = (qg << 2) + j;
                qf[j] = Qs4[(r << 4) | (e4 ^ (r & 15))];
            }
            #pragma unroll
            for (int i = 0; i < 4; i++) {
                int r = (kg << 2) + i;
                kf[i] = Ks4[(r << 4) | (e4 ^ (r & 15))];
            }
            #pragma unroll
            for (int i = 0; i < 4; i++)
                #pragma unroll
                for (int j = 0; j < 4; j++)
                    S[i][j] += kf[i].x * qf[j].x + kf[i].y * qf[j].y
                             + kf[i].z * qf[j].z + kf[i].w * qf[j].w;
        }

        // column (over k) max, shuffle-reduce across kg (lanes 0..15 / 16..31)
        float tmax[4];
        #pragma unroll
        for (int j = 0; j < 4; j++)
            tmax[j] = fmaxf(fmaxf(S[0][j], S[1][j]), fmaxf(S[2][j], S[3][j]));
        #pragma unroll
        for (int off = 8; off; off >>= 1)
            #pragma unroll
            for (int j = 0; j < 4; j++)
                tmax[j] = fmaxf(tmax[j], __shfl_xor_sync(0xffffffffu, tmax[j], off));
        if (kg == 0) {
            #pragma unroll
            for (int j = 0; j < 4; j++) {
                int q = (qg << 2) + j;
                float mo = m_s[q];
                float mn = fmaxf(mo, tmax[j]);
                m_s[q] = mn;
                alpha_s[q] = __expf(mo - mn);
            }
        }
        __syncthreads();

        float mloc[4], al[4], tsum[4];
        #pragma unroll
        for (int j = 0; j < 4; j++) {
            int q = (qg << 2) + j;
            mloc[j] = m_s[q]; al[j] = alpha_s[q]; tsum[j] = 0.f;
        }
        #pragma unroll
        for (int i = 0; i < 4; i++)
            #pragma unroll
            for (int j = 0; j < 4; j++) {
                float p = __expf(S[i][j] - mloc[j]);
                S[i][j] = p;
                tsum[j] += p;
            }
        #pragma unroll
        for (int off = 8; off; off >>= 1)
            #pragma unroll
            for (int j = 0; j < 4; j++)
                tsum[j] += __shfl_xor_sync(0xffffffffu, tsum[j], off);
        #pragma unroll
        for (int i = 0; i < 4; i++)
            #pragma unroll
            for (int j = 0; j < 4; j++) Oa[i][j] *= al[j];
        if (kg == 0) {
            #pragma unroll
            for (int j = 0; j < 4; j++) {
                int q = (qg << 2) + j;
                l_s[q] = l_s[q] * al[j] + tsum[j];
            }
        }
        // stage P (rows = k, cols = q)
        #pragma unroll
        for (int i = 0; i < 4; i++) {
            int r = (kg << 2) + i;
            Ps4[(r << 4) | (qg ^ (r & 15))] = make_float4(S[i][0], S[i][1], S[i][2], S[i][3]);
        }
        __syncthreads();

        // O[e][q] += sum_k V[k][e] * P[k][q]
        #pragma unroll 8
        for (int kk = 0; kk < 64; kk++) {
            float4 vv = Vs4[(kk << 4) | (kg ^ (kk & 15))];
            float4 pp = Ps4[(kk << 4) | (qg ^ (kk & 15))];
            float va[4] = {vv.x, vv.y, vv.z, vv.w};
            float pa[4] = {pp.x, pp.y, pp.z, pp.w};
            #pragma unroll
            for (int i = 0; i < 4; i++)
                #pragma unroll
                for (int j = 0; j < 4; j++) Oa[i][j] += va[i] * pa[j];
        }
        __syncthreads();  // protects Ks/Vs/Ps for next iteration
    }

    // epilogue: normalize, stage as [q][e] in Ps, write coalesced
    float linv[4];
    #pragma unroll
    for (int j = 0; j < 4; j++) linv[j] = 1.0f / l_s[(qg << 2) + j];
    #pragma unroll
    for (int j = 0; j < 4; j++) {
        int r = (qg << 2) + j;
        Ps4[(r << 4) | (kg ^ (r & 15))] =
            make_float4(Oa[0][j] * linv[j], Oa[1][j] * linv[j],
                        Oa[2][j] * linv[j], Oa[3][j] * linv[j]);
    }
    __syncthreads();
    float4* Og4 = (float4*)(g_vT + ((size_t)b * N + q0) * E);
    for (int idx = tid; idx < 1024; idx += 256) {
        int row = idx >> 4, s = idx & 15;
        Og4[idx] = Ps4[(row << 4) | (s ^ (row & 15))];
    }
}

// ---------------------------------------------------------------------------
// Output: y = gamma * (w_att @ v * (1/sqrt(E)) + b_att) + x
// grid: (N/64, B), 256 threads; w_att (64 KB) + att tile (padded) in smem
// ---------------------------------------------------------------------------
__global__ __launch_bounds__(256) void out_kernel(
    const float* __restrict__ x, const float* __restrict__ w_att,
    const float* __restrict__ b_att, const float* __restrict__ gamma,
    float* __restrict__ y)
{
    extern __shared__ float sm[];
    float* ws = sm;               // [256][64]
    float* as = sm + 256 * 64;    // [64][68]

    int b = blockIdx.y, n0 = blockIdx.x << 6;
    int tid = threadIdx.x;

    float4* ws4 = (float4*)ws;
    const float4* wg4 = (const float4*)w_att;
    for (int idx = tid; idx < 4096; idx += 256) ws4[idx] = wg4[idx];
    const float* src = g_vT + ((size_t)b * N + n0) * E;
    for (int idx = tid; idx < 4096; idx += 256) {
        int nl = idx >> 6, e = idx & 63;
        as[nl * 68 + e] = src[idx];
    }
    __syncthreads();

    int tx = tid & 63, ty = tid >> 6;  // ty 0..3
    const float* xcol = x + ((size_t)b * C) * N + n0 + tx;
    float* ycol = y + ((size_t)b * C) * N + n0 + tx;
    const float4* a4 = (const float4*)&as[tx * 68];

    for (int m0 = 0; m0 < 64; m0 += 4) {
        float acc[4] = {0.f, 0.f, 0.f, 0.f};
        #pragma unroll
        for (int e4 = 0; e4 < 16; e4++) {
            float4 a = a4[e4];
            #pragma unroll
            for (int mi = 0; mi < 4; mi++) {
                int c = ty + 4 * (m0 + mi);
                float4 w = ((const float4*)(ws + c * 64))[e4];
                acc[mi] += a.x * w.x + a.y * w.y + a.z * w.z + a.w * w.w;
            }
        }
        #pragma unroll
        for (int mi = 0; mi < 4; mi++) {
            int c = ty + 4 * (m0 + mi);
            float o = acc[mi] * 0.125f + b_att[c];  // 1/sqrt(64)
            ycol[(size_t)c * N] = gamma[c] * o + xcol[(size_t)c * N];
        }
    }
}

// ---------------------------------------------------------------------------
extern "C" void kernel_launch(void* const* d_in, const int* in_sizes, int n_in,
                              void* d_out, int out_size)
{
    const float* x  = (const float*)d_in[0];
    const float* wk = (const float*)d_in[1];
    const float* bk = (const float*)d_in[2];
    const float* wq = (const float*)d_in[3];
    const float* bq = (const float*)d_in[4];
    const float* wv = (const float*)d_in[5];
    const float* bv = (const float*)d_in[6];
    const float* wa = (const float*)d_in[7];
    const float* ba = (const float*)d_in[8];
    const float* gm = (const float*)d_in[9];
    float* y = (float*)d_out;

    cudaFuncSetAttribute(flash_kernel, cudaFuncAttributeMaxDynamicSharedMemorySize, 65536);
    cudaFuncSetAttribute(out_kernel,  cudaFuncAttributeMaxDynamicSharedMemorySize, 84000);

    proj_kernel<<<B * (N / 16), 256>>>(x, wk, bk, wq, bq, wv, bv);
    flash_kernel<<<dim3(N / 64, B), 256, 65536>>>();
    out_kernel<<<dim3(N / 64, B), 256, 82944>>>(x, wa, ba, gm, y);
}

// round 5
// speedup vs baseline: 3.1424x; 3.1424x over previous
#include <cuda_runtime.h>
#include <math.h>
#include <stdint.h>

static constexpr int B = 8, C = 256, E = 64, N = 4096;

__device__ float g_fT[B * N * E];  // key    [b][n][e]
__device__ float g_gT[B * N * E];  // query  [b][n][e]
__device__ float g_hE[B * E * N];  // value  [b][e][n]  (key-contiguous)
__device__ float g_vT[B * N * E];  // attn out [b][n][e]

// ---------------- helpers ----------------
__device__ __forceinline__ uint32_t smem_u32(const void* p) {
    uint32_t a;
    asm("{ .reg .u64 t; cvta.to.shared.u64 t, %1; cvt.u32.u64 %0, t; }" : "=r"(a) : "l"(p));
    return a;
}
__device__ __forceinline__ void cpasync16(uint32_t dst, const void* src) {
    asm volatile("cp.async.cg.shared.global [%0], [%1], 16;" :: "r"(dst), "l"(src));
}
#define CP_COMMIT() asm volatile("cp.async.commit_group;" ::: "memory")
#define CP_WAIT0()  asm volatile("cp.async.wait_group 0;" ::: "memory")

__device__ __forceinline__ uint32_t to_tf32(float v) {
    uint32_t u;
    asm("cvt.rna.tf32.f32 %0, %1;" : "=r"(u) : "f"(v));
    return u;
}
__device__ __forceinline__ void split_tf32(float v, uint32_t& hi, uint32_t& lo) {
    uint32_t h = to_tf32(v);
    lo = to_tf32(v - __uint_as_float(h));
    hi = h;
}
// D += A(16x8) * B(8x8), tf32 inputs, fp32 accum
__device__ __forceinline__ void mma8(float* d, const uint32_t* a, const uint32_t* b) {
    asm volatile(
        "mma.sync.aligned.m16n8k8.row.col.f32.tf32.tf32.f32 "
        "{%0,%1,%2,%3}, {%4,%5,%6,%7}, {%8,%9}, {%0,%1,%2,%3};"
        : "+f"(d[0]), "+f"(d[1]), "+f"(d[2]), "+f"(d[3])
        : "r"(a[0]), "r"(a[1]), "r"(a[2]), "r"(a[3]), "r"(b[0]), "r"(b[1]));
}

// ---------------------------------------------------------------------------
// Projection GEMM [192,256] x [256, 64-col tile]; 12x4 microtile per thread.
// grid (N/64, B), 256 threads, 67584 B dyn smem.
// ---------------------------------------------------------------------------
__global__ __launch_bounds__(256) void proj_kernel(
    const float* __restrict__ x,
    const float* __restrict__ wk, const float* __restrict__ bk,
    const float* __restrict__ wq, const float* __restrict__ bq,
    const float* __restrict__ wv, const float* __restrict__ bv)
{
    extern __shared__ float psm[];
    float* xs = psm;              // [64 c][68 n]
    float* ws = psm + 64 * 68;    // [64 c][196 r]

    const int b  = blockIdx.y;
    const int n0 = blockIdx.x << 6;
    const int tid = threadIdx.x;
    const float* xb = x + (size_t)b * C * N;
    const int rg = tid >> 4;      // 12-row group
    const int cg = tid & 15;      // 4-col group

    float acc[12][4];
    #pragma unroll
    for (int i = 0; i < 12; i++)
        #pragma unroll
        for (int j = 0; j < 4; j++) acc[i][j] = 0.f;

    for (int c0 = 0; c0 < C; c0 += 64) {
        __syncthreads();
        for (int i = tid; i < 1024; i += 256) {
            int c = i >> 4, n4 = (i & 15) << 2;
            *(float4*)&xs[c * 68 + n4] = *(const float4*)&xb[(size_t)(c0 + c) * N + n0 + n4];
        }
        for (int i = tid; i < 12288; i += 256) {
            int r = i >> 6, c = i & 63;
            float v;
            if (r < 64)       v = wk[r * C + c0 + c];
            else if (r < 128) v = wq[(r - 64) * C + c0 + c];
            else              v = wv[(r - 128) * C + c0 + c];
            ws[c * 196 + r] = v;
        }
        __syncthreads();
        #pragma unroll 4
        for (int c = 0; c < 64; ++c) {
            float4 xv = *(float4*)&xs[c * 68 + (cg << 2)];
            const float4* wp = (const float4*)&ws[c * 196 + rg * 12];
            float4 w0 = wp[0], w1 = wp[1], w2 = wp[2];
            float wr[12] = {w0.x, w0.y, w0.z, w0.w, w1.x, w1.y, w1.z, w1.w,
                            w2.x, w2.y, w2.z, w2.w};
            #pragma unroll
            for (int i = 0; i < 12; i++) {
                acc[i][0] += wr[i] * xv.x; acc[i][1] += wr[i] * xv.y;
                acc[i][2] += wr[i] * xv.z; acc[i][3] += wr[i] * xv.w;
            }
        }
    }
    #pragma unroll
    for (int i = 0; i < 12; i++) {
        int r = rg * 12 + i;
        float bias = (r < 64) ? bk[r] : (r < 128 ? bq[r - 64] : bv[r - 128]);
        #pragma unroll
        for (int j = 0; j < 4; j++) {
            int n = n0 + (cg << 2) + j;
            float v = acc[i][j] * 0.0625f + bias;
            if (r < 64)       g_fT[((size_t)b * N + n) * E + r] = v;
            else if (r < 128) g_gT[((size_t)b * N + n) * E + (r - 64)] = v;
            else              g_hE[((size_t)b * E + (r - 128)) * N + n] = v;
        }
    }
}

// ---------------------------------------------------------------------------
// Flash attention via mma.sync tf32 (3xtf32 for S, 1x for PV).
// CTA: 256 thr = 8 warps x 16 q-rows (BLOCK_M=128), BLOCK_N=64 keys.
// smem floats: Khi[2][64][68] Klo[2][64][68] Vs[2][64][68] Ps[128][68]
// grid (N/128, B) = (32, 8), 139264 B dyn smem. 64 key tiles.
// ---------------------------------------------------------------------------
static constexpr int KHI0 = 0;
static constexpr int KLO0 = 8704;    // 2*4352
static constexpr int VS0  = 17408;
static constexpr int PS0  = 26112;
static constexpr int NT   = N / 64;  // 64 key tiles  (bug fix: was 32)

__global__ __launch_bounds__(256, 1) void flash_mma()
{
    extern __shared__ float fsm[];
    const int tid = threadIdx.x;
    const int lane = tid & 31, w = tid >> 5;
    const int tig = lane & 3, gid = lane >> 2;   // mma frag coords
    const int b = blockIdx.y, q0 = blockIdx.x << 7;

    const float* Kg = g_fT + (size_t)b * N * E;
    const float* Vg = g_hE + (size_t)b * E * N;
    const float* Qg = g_gT + ((size_t)b * N + q0) * E;

    // stage Q (raw) into Ps
    for (int i = tid; i < 2048; i += 256) {
        int row = i >> 4, c4 = (i & 15) << 2;
        cpasync16(smem_u32(fsm + PS0 + row * 68 + c4), Qg + row * 64 + c4);
    }
    CP_COMMIT();

    // tile 0: K via LDG+split, V via cp.async
    {
        int row = tid >> 2, cb = (tid & 3) << 2;
        float4 kv[4];
        #pragma unroll
        for (int i = 0; i < 4; i++)
            kv[i] = *(const float4*)(Kg + (size_t)row * 64 + cb + 16 * i);
        #pragma unroll
        for (int i = 0; i < 4; i++)
            cpasync16(smem_u32(fsm + VS0 + row * 68 + cb + 16 * i),
                      Vg + (size_t)row * N + cb + 16 * i);
        CP_COMMIT();
        #pragma unroll
        for (int i = 0; i < 4; i++) {
            uint32_t h0, l0v, h1, l1v, h2, l2v, h3, l3v;
            split_tf32(kv[i].x, h0, l0v); split_tf32(kv[i].y, h1, l1v);
            split_tf32(kv[i].z, h2, l2v); split_tf32(kv[i].w, h3, l3v);
            float* dh = fsm + KHI0 + row * 68 + cb + 16 * i;
            float* dl = fsm + KLO0 + row * 68 + cb + 16 * i;
            *(float4*)dh = make_float4(__uint_as_float(h0), __uint_as_float(h1),
                                       __uint_as_float(h2), __uint_as_float(h3));
            *(float4*)dl = make_float4(__uint_as_float(l0v), __uint_as_float(l1v),
                                       __uint_as_float(l2v), __uint_as_float(l3v));
        }
    }
    CP_WAIT0();
    __syncthreads();

    // Q fragments (hi/lo), register resident
    uint32_t qhi[8][4], qlo[8][4];
    {
        const float* Qs = fsm + PS0 + (w * 16) * 68;
        #pragma unroll
        for (int ks = 0; ks < 8; ks++) {
            int e = tig + 8 * ks;
            split_tf32(Qs[gid * 68 + e],           qhi[ks][0], qlo[ks][0]);
            split_tf32(Qs[(gid + 8) * 68 + e],     qhi[ks][1], qlo[ks][1]);
            split_tf32(Qs[gid * 68 + e + 4],       qhi[ks][2], qlo[ks][2]);
            split_tf32(Qs[(gid + 8) * 68 + e + 4], qhi[ks][3], qlo[ks][3]);
        }
    }
    __syncthreads();   // Ps free for P staging

    float O[8][4];
    #pragma unroll
    for (int j = 0; j < 8; j++)
        #pragma unroll
        for (int i = 0; i < 4; i++) O[j][i] = 0.f;
    float m0 = -1e30f, m1 = -1e30f, l0 = 0.f, l1 = 0.f;

    const int r0 = w * 16 + gid;   // this thread's first q-row in Ps

    for (int t = 0; t < NT; ++t) {
        const int buf = t & 1, nb = buf ^ 1;
        float4 kst[4];
        const bool pref = (t < NT - 1);
        const int rowf = tid >> 2, cbf = (tid & 3) << 2;
        if (pref) {
            int k0n = (t + 1) << 6;
            #pragma unroll
            for (int i = 0; i < 4; i++)
                kst[i] = *(const float4*)(Kg + (size_t)(k0n + rowf) * 64 + cbf + 16 * i);
            #pragma unroll
            for (int i = 0; i < 4; i++)
                cpasync16(smem_u32(fsm + VS0 + nb * 4352 + rowf * 68 + cbf + 16 * i),
                          Vg + (size_t)rowf * N + k0n + cbf + 16 * i);
            CP_COMMIT();
        }

        // ---- S = Q K^T via 3xtf32 ----
        float S[8][4];
        #pragma unroll
        for (int j = 0; j < 8; j++)
            #pragma unroll
            for (int i = 0; i < 4; i++) S[j][i] = 0.f;
        {
            const float* Kh = fsm + KHI0 + buf * 4352;
            const float* Kl = fsm + KLO0 + buf * 4352;
            #pragma unroll
            for (int ks = 0; ks < 8; ks++) {
                int e = tig + 8 * ks;
                #pragma unroll
                for (int j = 0; j < 8; j++) {
                    int key = gid + 8 * j;
                    uint32_t bh[2], bl[2];
                    bh[0] = __float_as_uint(Kh[key * 68 + e]);
                    bh[1] = __float_as_uint(Kh[key * 68 + e + 4]);
                    bl[0] = __float_as_uint(Kl[key * 68 + e]);
                    bl[1] = __float_as_uint(Kl[key * 68 + e + 4]);
                    mma8(S[j], qhi[ks], bh);
                    mma8(S[j], qlo[ks], bh);
                    mma8(S[j], qhi[ks], bl);
                }
            }
        }

        // ---- online softmax (rows r0 and r0+8) ----
        float c0 = -1e30f, c1 = -1e30f;
        #pragma unroll
        for (int j = 0; j < 8; j++) {
            c0 = fmaxf(c0, fmaxf(S[j][0], S[j][1]));
            c1 = fmaxf(c1, fmaxf(S[j][2], S[j][3]));
        }
        c0 = fmaxf(c0, __shfl_xor_sync(0xffffffffu, c0, 1));
        c0 = fmaxf(c0, __shfl_xor_sync(0xffffffffu, c0, 2));
        c1 = fmaxf(c1, __shfl_xor_sync(0xffffffffu, c1, 1));
        c1 = fmaxf(c1, __shfl_xor_sync(0xffffffffu, c1, 2));
        float mn0 = fmaxf(m0, c0), mn1 = fmaxf(m1, c1);
        float a0 = __expf(m0 - mn0), a1 = __expf(m1 - mn1);
        m0 = mn0; m1 = mn1;

        float s0 = 0.f, s1 = 0.f;
        #pragma unroll
        for (int j = 0; j < 8; j++) {
            float p00 = __expf(S[j][0] - m0), p01 = __expf(S[j][1] - m0);
            float p10 = __expf(S[j][2] - m1), p11 = __expf(S[j][3] - m1);
            s0 += p00 + p01; s1 += p10 + p11;
            int col = 8 * j + 2 * tig;
            *(uint2*)(fsm + PS0 + r0 * 68 + col) = make_uint2(to_tf32(p00), to_tf32(p01));
            *(uint2*)(fsm + PS0 + (r0 + 8) * 68 + col) = make_uint2(to_tf32(p10), to_tf32(p11));
        }
        s0 += __shfl_xor_sync(0xffffffffu, s0, 1);
        s0 += __shfl_xor_sync(0xffffffffu, s0, 2);
        s1 += __shfl_xor_sync(0xffffffffu, s1, 1);
        s1 += __shfl_xor_sync(0xffffffffu, s1, 2);
        l0 = l0 * a0 + s0;
        l1 = l1 * a1 + s1;
        #pragma unroll
        for (int j = 0; j < 8; j++) {
            O[j][0] *= a0; O[j][1] *= a0; O[j][2] *= a1; O[j][3] *= a1;
        }
        __syncwarp();

        // ---- O += P V^T ----
        {
            const float* Vs = fsm + VS0 + buf * 4352;
            #pragma unroll
            for (int ks = 0; ks < 8; ks++) {
                int k = tig + 8 * ks;
                uint32_t pa[4];
                pa[0] = __float_as_uint(fsm[PS0 + r0 * 68 + k]);
                pa[1] = __float_as_uint(fsm[PS0 + (r0 + 8) * 68 + k]);
                pa[2] = __float_as_uint(fsm[PS0 + r0 * 68 + k + 4]);
                pa[3] = __float_as_uint(fsm[PS0 + (r0 + 8) * 68 + k + 4]);
                #pragma unroll
                for (int j = 0; j < 8; j++) {
                    int e = gid + 8 * j;
                    uint32_t vb[2];
                    vb[0] = __float_as_uint(Vs[e * 68 + k]);
                    vb[1] = __float_as_uint(Vs[e * 68 + k + 4]);
                    mma8(O[j], pa, vb);
                }
            }
        }
        __syncwarp();

        // stage next K tile
        if (pref) {
            #pragma unroll
            for (int i = 0; i < 4; i++) {
                uint32_t h0, l0v, h1, l1v, h2, l2v, h3, l3v;
                split_tf32(kst[i].x, h0, l0v); split_tf32(kst[i].y, h1, l1v);
                split_tf32(kst[i].z, h2, l2v); split_tf32(kst[i].w, h3, l3v);
                float* dh = fsm + KHI0 + nb * 4352 + rowf * 68 + cbf + 16 * i;
                float* dl = fsm + KLO0 + nb * 4352 + rowf * 68 + cbf + 16 * i;
                *(float4*)dh = make_float4(__uint_as_float(h0), __uint_as_float(h1),
                                           __uint_as_float(h2), __uint_as_float(h3));
                *(float4*)dl = make_float4(__uint_as_float(l0v), __uint_as_float(l1v),
                                           __uint_as_float(l2v), __uint_as_float(l3v));
            }
        }
        CP_WAIT0();
        __syncthreads();
    }

    // ---- epilogue: O/l -> Ps -> gmem ----
    {
        float i0 = 1.f / l0, i1 = 1.f / l1;
        #pragma unroll
        for (int j = 0; j < 8; j++) {
            int col = 8 * j + 2 * tig;
            *(float2*)(fsm + PS0 + r0 * 68 + col) = make_float2(O[j][0] * i0, O[j][1] * i0);
            *(float2*)(fsm + PS0 + (r0 + 8) * 68 + col) = make_float2(O[j][2] * i1, O[j][3] * i1);
        }
    }
    __syncthreads();
    {
        float* dst = g_vT + ((size_t)b * N + q0) * E;
        for (int i = tid; i < 2048; i += 256) {
            int row = i >> 4, c4 = (i & 15) << 2;
            *(float4*)(dst + (size_t)row * 64 + c4) = *(float4*)(fsm + PS0 + row * 68 + c4);
        }
    }
}

// ---------------------------------------------------------------------------
// Output: y = gamma * (w_att @ v / 8 + b_att) + x   (unchanged, known-good)
// ---------------------------------------------------------------------------
__global__ __launch_bounds__(256) void out_kernel(
    const float* __restrict__ x, const float* __restrict__ w_att,
    const float* __restrict__ b_att, const float* __restrict__ gamma,
    float* __restrict__ y)
{
    extern __shared__ float sm[];
    float* ws = sm;               // [256][64]
    float* as = sm + 256 * 64;    // [64][68]
    int b = blockIdx.y, n0 = blockIdx.x << 6;
    int tid = threadIdx.x;

    float4* ws4 = (float4*)ws;
    const float4* wg4 = (const float4*)w_att;
    for (int idx = tid; idx < 4096; idx += 256) ws4[idx] = wg4[idx];
    const float* src = g_vT + ((size_t)b * N + n0) * E;
    for (int idx = tid; idx < 4096; idx += 256) {
        int nl = idx >> 6, e = idx & 63;
        as[nl * 68 + e] = src[idx];
    }
    __syncthreads();

    int tx = tid & 63, ty = tid >> 6;
    const float* xcol = x + ((size_t)b * C) * N + n0 + tx;
    float* ycol = y + ((size_t)b * C) * N + n0 + tx;
    const float4* a4 = (const float4*)&as[tx * 68];

    for (int m0 = 0; m0 < 64; m0 += 4) {
        float acc[4] = {0.f, 0.f, 0.f, 0.f};
        #pragma unroll
        for (int e4 = 0; e4 < 16; e4++) {
            float4 a = a4[e4];
            #pragma unroll
            for (int mi = 0; mi < 4; mi++) {
                int c = ty + 4 * (m0 + mi);
                float4 wv = ((const float4*)(ws + c * 64))[e4];
                acc[mi] += a.x * wv.x + a.y * wv.y + a.z * wv.z + a.w * wv.w;
            }
        }
        #pragma unroll
        for (int mi = 0; mi < 4; mi++) {
            int c = ty + 4 * (m0 + mi);
            float o = acc[mi] * 0.125f + b_att[c];
            ycol[(size_t)c * N] = gamma[c] * o + xcol[(size_t)c * N];
        }
    }
}

// ---------------------------------------------------------------------------
extern "C" void kernel_launch(void* const* d_in, const int* in_sizes, int n_in,
                              void* d_out, int out_size)
{
    const float* x  = (const float*)d_in[0];
    const float* wk = (const float*)d_in[1];
    const float* bk = (const float*)d_in[2];
    const float* wq = (const float*)d_in[3];
    const float* bq = (const float*)d_in[4];
    const float* wv = (const float*)d_in[5];
    const float* bv = (const float*)d_in[6];
    const float* wa = (const float*)d_in[7];
    const float* ba = (const float*)d_in[8];
    const float* gm = (const float*)d_in[9];
    float* y = (float*)d_out;

    cudaFuncSetAttribute(proj_kernel, cudaFuncAttributeMaxDynamicSharedMemorySize, 69632);
    cudaFuncSetAttribute(flash_mma,  cudaFuncAttributeMaxDynamicSharedMemorySize, 139264);
    cudaFuncSetAttribute(out_kernel, cudaFuncAttributeMaxDynamicSharedMemorySize, 84000);

    proj_kernel<<<dim3(N / 64, B), 256, 67584>>>(x, wk, bk, wq, bq, wv, bv);
    flash_mma<<<dim3(N / 128, B), 256, 139264>>>();
    out_kernel<<<dim3(N / 64, B), 256, 82944>>>(x, wa, ba, gm, y);
}

// round 6
// speedup vs baseline: 3.5596x; 1.1328x over previous
#include <cuda_runtime.h>
#include <math.h>
#include <stdint.h>

static constexpr int B = 8, C = 256, E = 64, N = 4096;

__device__ float g_fT[B * N * E];  // key    [b][n][e]
__device__ float g_gT[B * N * E];  // query  [b][n][e]
__device__ float g_hE[B * E * N];  // value  [b][e][n]  (key-contiguous)
__device__ float g_vT[B * N * E];  // attn out [b][n][e]

// ---------------- helpers ----------------
__device__ __forceinline__ uint32_t smem_u32(const void* p) {
    uint32_t a;
    asm("{ .reg .u64 t; cvta.to.shared.u64 t, %1; cvt.u32.u64 %0, t; }" : "=r"(a) : "l"(p));
    return a;
}
__device__ __forceinline__ void cpasync16(uint32_t dst, const void* src) {
    asm volatile("cp.async.cg.shared.global [%0], [%1], 16;" :: "r"(dst), "l"(src));
}
#define CP_COMMIT() asm volatile("cp.async.commit_group;" ::: "memory")
#define CP_WAIT0()  asm volatile("cp.async.wait_group 0;" ::: "memory")

__device__ __forceinline__ uint32_t to_tf32(float v) {
    uint32_t u;
    asm("cvt.rna.tf32.f32 %0, %1;" : "=r"(u) : "f"(v));
    return u;
}
__device__ __forceinline__ void split_tf32(float v, uint32_t& hi, uint32_t& lo) {
    uint32_t h = to_tf32(v);
    lo = to_tf32(v - __uint_as_float(h));
    hi = h;
}
// D += A(16x8) * B(8x8), tf32 inputs, fp32 accum
__device__ __forceinline__ void mma8(float* d, const uint32_t* a, const uint32_t* b) {
    asm volatile(
        "mma.sync.aligned.m16n8k8.row.col.f32.tf32.tf32.f32 "
        "{%0,%1,%2,%3}, {%4,%5,%6,%7}, {%8,%9}, {%0,%1,%2,%3};"
        : "+f"(d[0]), "+f"(d[1]), "+f"(d[2]), "+f"(d[3])
        : "r"(a[0]), "r"(a[1]), "r"(a[2]), "r"(a[3]), "r"(b[0]), "r"(b[1]));
}

// ---------------------------------------------------------------------------
// Projection GEMM [192,256] x [256, 64-col tile]; 8x4 microtile per thread.
// grid (N/64, B), 384 threads, 67584 B dyn smem, 2 CTAs/SM.
// ---------------------------------------------------------------------------
__global__ __launch_bounds__(384, 2) void proj_kernel(
    const float* __restrict__ x,
    const float* __restrict__ wk, const float* __restrict__ bk,
    const float* __restrict__ wq, const float* __restrict__ bq,
    const float* __restrict__ wv, const float* __restrict__ bv)
{
    extern __shared__ float psm[];
    float* xs = psm;              // [64 c][68 n]
    float* ws = psm + 64 * 68;    // [64 c][196 r]

    const int b  = blockIdx.y;
    const int n0 = blockIdx.x << 6;
    const int tid = threadIdx.x;
    const float* xb = x + (size_t)b * C * N;
    const int rg = tid >> 4;      // 8-row group (0..23)
    const int cg = tid & 15;      // 4-col group

    float acc[8][4];
    #pragma unroll
    for (int i = 0; i < 8; i++)
        #pragma unroll
        for (int j = 0; j < 4; j++) acc[i][j] = 0.f;

    for (int c0 = 0; c0 < C; c0 += 64) {
        __syncthreads();
        for (int i = tid; i < 1024; i += 384) {
            int c = i >> 4, n4 = (i & 15) << 2;
            *(float4*)&xs[c * 68 + n4] = *(const float4*)&xb[(size_t)(c0 + c) * N + n0 + n4];
        }
        for (int i = tid; i < 12288; i += 384) {
            int r = i >> 6, c = i & 63;
            float v;
            if (r < 64)       v = wk[r * C + c0 + c];
            else if (r < 128) v = wq[(r - 64) * C + c0 + c];
            else              v = wv[(r - 128) * C + c0 + c];
            ws[c * 196 + r] = v;
        }
        __syncthreads();
        #pragma unroll 4
        for (int c = 0; c < 64; ++c) {
            float4 xv = *(float4*)&xs[c * 68 + (cg << 2)];
            const float4* wp = (const float4*)&ws[c * 196 + rg * 8];
            float4 w0 = wp[0], w1 = wp[1];
            float wr[8] = {w0.x, w0.y, w0.z, w0.w, w1.x, w1.y, w1.z, w1.w};
            #pragma unroll
            for (int i = 0; i < 8; i++) {
                acc[i][0] += wr[i] * xv.x; acc[i][1] += wr[i] * xv.y;
                acc[i][2] += wr[i] * xv.z; acc[i][3] += wr[i] * xv.w;
            }
        }
    }
    #pragma unroll
    for (int i = 0; i < 8; i++) {
        int r = rg * 8 + i;
        float bias = (r < 64) ? bk[r] : (r < 128 ? bq[r - 64] : bv[r - 128]);
        #pragma unroll
        for (int j = 0; j < 4; j++) {
            int n = n0 + (cg << 2) + j;
            float v = acc[i][j] * 0.0625f + bias;
            if (r < 64)       g_fT[((size_t)b * N + n) * E + r] = v;
            else if (r < 128) g_gT[((size_t)b * N + n) * E + (r - 64)] = v;
            else              g_hE[((size_t)b * E + (r - 128)) * N + n] = v;
        }
    }
}

// ---------------------------------------------------------------------------
// Flash attention via mma.sync tf32 (2-term K-split for S, 1x for PV).
// CTA: 256 thr = 8 warps x 16 q-rows (BLOCK_M=128), BLOCK_N=64 keys.
// smem floats: Khi[64][68] Klo[64][68] Vs[2][64][68] Ps[128][68] = 104448 B
// grid (N/128, B) = (32, 8), 2 CTAs/SM. 64 key tiles.
// ---------------------------------------------------------------------------
static constexpr int KHI0 = 0;
static constexpr int KLO0 = 4352;
static constexpr int VS0  = 8704;     // 2 x 4352
static constexpr int PS0  = 17408;
static constexpr int NT   = N / 64;   // 64 key tiles

__global__ __launch_bounds__(256, 2) void flash_mma()
{
    extern __shared__ float fsm[];
    const int tid = threadIdx.x;
    const int lane = tid & 31, w = tid >> 5;
    const int tig = lane & 3, gid = lane >> 2;   // mma frag coords
    const int b = blockIdx.y, q0 = blockIdx.x << 7;

    const float* Kg = g_fT + (size_t)b * N * E;
    const float* Vg = g_hE + (size_t)b * E * N;
    const float* Qg = g_gT + ((size_t)b * N + q0) * E;

    const int rowf = tid >> 2, cbf = (tid & 3) << 2;

    // stage Q (raw) into Ps
    for (int i = tid; i < 2048; i += 256) {
        int row = i >> 4, c4 = (i & 15) << 2;
        cpasync16(smem_u32(fsm + PS0 + row * 68 + c4), Qg + row * 64 + c4);
    }
    CP_COMMIT();

    // tile 0: K via LDG+split, V via cp.async
    {
        float4 kv[4];
        #pragma unroll
        for (int i = 0; i < 4; i++)
            kv[i] = *(const float4*)(Kg + (size_t)rowf * 64 + cbf + 16 * i);
        #pragma unroll
        for (int i = 0; i < 4; i++)
            cpasync16(smem_u32(fsm + VS0 + rowf * 68 + cbf + 16 * i),
                      Vg + (size_t)rowf * N + cbf + 16 * i);
        CP_COMMIT();
        #pragma unroll
        for (int i = 0; i < 4; i++) {
            uint32_t h0, l0v, h1, l1v, h2, l2v, h3, l3v;
            split_tf32(kv[i].x, h0, l0v); split_tf32(kv[i].y, h1, l1v);
            split_tf32(kv[i].z, h2, l2v); split_tf32(kv[i].w, h3, l3v);
            float* dh = fsm + KHI0 + rowf * 68 + cbf + 16 * i;
            float* dl = fsm + KLO0 + rowf * 68 + cbf + 16 * i;
            *(float4*)dh = make_float4(__uint_as_float(h0), __uint_as_float(h1),
                                       __uint_as_float(h2), __uint_as_float(h3));
            *(float4*)dl = make_float4(__uint_as_float(l0v), __uint_as_float(l1v),
                                       __uint_as_float(l2v), __uint_as_float(l3v));
        }
    }
    CP_WAIT0();
    __syncthreads();

    // Q fragments (single tf32), register resident: 32 regs
    uint32_t qt[8][4];
    {
        const float* Qs = fsm + PS0 + (w * 16) * 68;
        #pragma unroll
        for (int ks = 0; ks < 8; ks++) {
            int e = tig + 8 * ks;
            qt[ks][0] = to_tf32(Qs[gid * 68 + e]);
            qt[ks][1] = to_tf32(Qs[(gid + 8) * 68 + e]);
            qt[ks][2] = to_tf32(Qs[gid * 68 + e + 4]);
            qt[ks][3] = to_tf32(Qs[(gid + 8) * 68 + e + 4]);
        }
    }
    __syncthreads();   // Ps free for P staging

    float O[8][4];
    #pragma unroll
    for (int j = 0; j < 8; j++)
        #pragma unroll
        for (int i = 0; i < 4; i++) O[j][i] = 0.f;
    float m0 = -1e30f, m1 = -1e30f, l0 = 0.f, l1 = 0.f;

    const int r0 = w * 16 + gid;   // this thread's first q-row in Ps

    for (int t = 0; t < NT; ++t) {
        const int buf = t & 1, nb = buf ^ 1;
        const bool pref = (t < NT - 1);
        const int k0n = (t + 1) << 6;
        if (pref) {   // V prefetch (async, into other buffer)
            #pragma unroll
            for (int i = 0; i < 4; i++)
                cpasync16(smem_u32(fsm + VS0 + nb * 4352 + rowf * 68 + cbf + 16 * i),
                          Vg + (size_t)rowf * N + k0n + cbf + 16 * i);
            CP_COMMIT();
        }

        // ---- S = qt * (Khi + Klo)  (exact K, rounded Q) ----
        float S[8][4];
        #pragma unroll
        for (int j = 0; j < 8; j++)
            #pragma unroll
            for (int i = 0; i < 4; i++) S[j][i] = 0.f;
        {
            const float* Kh = fsm + KHI0;
            const float* Kl = fsm + KLO0;
            #pragma unroll
            for (int ks = 0; ks < 8; ks++) {
                int e = tig + 8 * ks;
                #pragma unroll
                for (int j = 0; j < 8; j++) {
                    int key = gid + 8 * j;
                    uint32_t bh[2], bl[2];
                    bh[0] = __float_as_uint(Kh[key * 68 + e]);
                    bh[1] = __float_as_uint(Kh[key * 68 + e + 4]);
                    bl[0] = __float_as_uint(Kl[key * 68 + e]);
                    bl[1] = __float_as_uint(Kl[key * 68 + e + 4]);
                    mma8(S[j], qt[ks], bh);
                    mma8(S[j], qt[ks], bl);
                }
            }
        }

        // ---- online softmax (rows r0 and r0+8) ----
        float c0 = -1e30f, c1 = -1e30f;
        #pragma unroll
        for (int j = 0; j < 8; j++) {
            c0 = fmaxf(c0, fmaxf(S[j][0], S[j][1]));
            c1 = fmaxf(c1, fmaxf(S[j][2], S[j][3]));
        }
        c0 = fmaxf(c0, __shfl_xor_sync(0xffffffffu, c0, 1));
        c0 = fmaxf(c0, __shfl_xor_sync(0xffffffffu, c0, 2));
        c1 = fmaxf(c1, __shfl_xor_sync(0xffffffffu, c1, 1));
        c1 = fmaxf(c1, __shfl_xor_sync(0xffffffffu, c1, 2));
        float mn0 = fmaxf(m0, c0), mn1 = fmaxf(m1, c1);
        float a0 = __expf(m0 - mn0), a1 = __expf(m1 - mn1);
        m0 = mn0; m1 = mn1;

        float s0 = 0.f, s1 = 0.f;
        #pragma unroll
        for (int j = 0; j < 8; j++) {
            float p00 = __expf(S[j][0] - m0), p01 = __expf(S[j][1] - m0);
            float p10 = __expf(S[j][2] - m1), p11 = __expf(S[j][3] - m1);
            s0 += p00 + p01; s1 += p10 + p11;
            int col = 8 * j + 2 * tig;
            *(uint2*)(fsm + PS0 + r0 * 68 + col) = make_uint2(to_tf32(p00), to_tf32(p01));
            *(uint2*)(fsm + PS0 + (r0 + 8) * 68 + col) = make_uint2(to_tf32(p10), to_tf32(p11));
        }
        s0 += __shfl_xor_sync(0xffffffffu, s0, 1);
        s0 += __shfl_xor_sync(0xffffffffu, s0, 2);
        s1 += __shfl_xor_sync(0xffffffffu, s1, 1);
        s1 += __shfl_xor_sync(0xffffffffu, s1, 2);
        l0 = l0 * a0 + s0;
        l1 = l1 * a1 + s1;
        #pragma unroll
        for (int j = 0; j < 8; j++) {
            O[j][0] *= a0; O[j][1] *= a0; O[j][2] *= a1; O[j][3] *= a1;
        }

        // All warps done reading K smem + each warp's Ps rows written
        __syncthreads();

        // K prefetch into registers (latency hides under PV mma)
        float4 kst[4];
        if (pref) {
            #pragma unroll
            for (int i = 0; i < 4; i++)
                kst[i] = *(const float4*)(Kg + (size_t)(k0n + rowf) * 64 + cbf + 16 * i);
        }

        // ---- O += P V^T ----
        {
            const float* Vs = fsm + VS0 + buf * 4352;
            #pragma unroll
            for (int ks = 0; ks < 8; ks++) {
                int k = tig + 8 * ks;
                uint32_t pa[4];
                pa[0] = __float_as_uint(fsm[PS0 + r0 * 68 + k]);
                pa[1] = __float_as_uint(fsm[PS0 + (r0 + 8) * 68 + k]);
                pa[2] = __float_as_uint(fsm[PS0 + r0 * 68 + k + 4]);
                pa[3] = __float_as_uint(fsm[PS0 + (r0 + 8) * 68 + k + 4]);
                #pragma unroll
                for (int j = 0; j < 8; j++) {
                    int e = gid + 8 * j;
                    uint32_t vb[2];
                    vb[0] = __float_as_uint(Vs[e * 68 + k]);
                    vb[1] = __float_as_uint(Vs[e * 68 + k + 4]);
                    mma8(O[j], pa, vb);
                }
            }
        }

        // stage next K tile (single buffer; safe after the barrier above)
        if (pref) {
            #pragma unroll
            for (int i = 0; i < 4; i++) {
                uint32_t h0, l0v, h1, l1v, h2, l2v, h3, l3v;
                split_tf32(kst[i].x, h0, l0v); split_tf32(kst[i].y, h1, l1v);
                split_tf32(kst[i].z, h2, l2v); split_tf32(kst[i].w, h3, l3v);
                float* dh = fsm + KHI0 + rowf * 68 + cbf + 16 * i;
                float* dl = fsm + KLO0 + rowf * 68 + cbf + 16 * i;
                *(float4*)dh = make_float4(__uint_as_float(h0), __uint_as_float(h1),
                                           __uint_as_float(h2), __uint_as_float(h3));
                *(float4*)dl = make_float4(__uint_as_float(l0v), __uint_as_float(l1v),
                                           __uint_as_float(l2v), __uint_as_float(l3v));
            }
        }
        CP_WAIT0();
        __syncthreads();
    }

    // ---- epilogue: O/l -> Ps -> gmem ----
    {
        float i0 = 1.f / l0, i1 = 1.f / l1;
        #pragma unroll
        for (int j = 0; j < 8; j++) {
            int col = 8 * j + 2 * tig;
            *(float2*)(fsm + PS0 + r0 * 68 + col) = make_float2(O[j][0] * i0, O[j][1] * i0);
            *(float2*)(fsm + PS0 + (r0 + 8) * 68 + col) = make_float2(O[j][2] * i1, O[j][3] * i1);
        }
    }
    __syncthreads();
    {
        float* dst = g_vT + ((size_t)b * N + q0) * E;
        for (int i = tid; i < 2048; i += 256) {
            int row = i >> 4, c4 = (i & 15) << 2;
            *(float4*)(dst + (size_t)row * 64 + c4) = *(float4*)(fsm + PS0 + row * 68 + c4);
        }
    }
}

// ---------------------------------------------------------------------------
// Output: y = gamma * (w_att @ v / 8 + b_att) + x   (unchanged, known-good)
// ---------------------------------------------------------------------------
__global__ __launch_bounds__(256) void out_kernel(
    const float* __restrict__ x, const float* __restrict__ w_att,
    const float* __restrict__ b_att, const float* __restrict__ gamma,
    float* __restrict__ y)
{
    extern __shared__ float sm[];
    float* ws = sm;               // [256][64]
    float* as = sm + 256 * 64;    // [64][68]
    int b = blockIdx.y, n0 = blockIdx.x << 6;
    int tid = threadIdx.x;

    float4* ws4 = (float4*)ws;
    const float4* wg4 = (const float4*)w_att;
    for (int idx = tid; idx < 4096; idx += 256) ws4[idx] = wg4[idx];
    const float* src = g_vT + ((size_t)b * N + n0) * E;
    for (int idx = tid; idx < 4096; idx += 256) {
        int nl = idx >> 6, e = idx & 63;
        as[nl * 68 + e] = src[idx];
    }
    __syncthreads();

    int tx = tid & 63, ty = tid >> 6;
    const float* xcol = x + ((size_t)b * C) * N + n0 + tx;
    float* ycol = y + ((size_t)b * C) * N + n0 + tx;
    const float4* a4 = (const float4*)&as[tx * 68];

    for (int m0 = 0; m0 < 64; m0 += 4) {
        float acc[4] = {0.f, 0.f, 0.f, 0.f};
        #pragma unroll
        for (int e4 = 0; e4 < 16; e4++) {
            float4 a = a4[e4];
            #pragma unroll
            for (int mi = 0; mi < 4; mi++) {
                int c = ty + 4 * (m0 + mi);
                float4 wv = ((const float4*)(ws + c * 64))[e4];
                acc[mi] += a.x * wv.x + a.y * wv.y + a.z * wv.z + a.w * wv.w;
            }
        }
        #pragma unroll
        for (int mi = 0; mi < 4; mi++) {
            int c = ty + 4 * (m0 + mi);
            float o = acc[mi] * 0.125f + b_att[c];
            ycol[(size_t)c * N] = gamma[c] * o + xcol[(size_t)c * N];
        }
    }
}

// ---------------------------------------------------------------------------
extern "C" void kernel_launch(void* const* d_in, const int* in_sizes, int n_in,
                              void* d_out, int out_size)
{
    const float* x  = (const float*)d_in[0];
    const float* wk = (const float*)d_in[1];
    const float* bk = (const float*)d_in[2];
    const float* wq = (const float*)d_in[3];
    const float* bq = (const float*)d_in[4];
    const float* wv = (const float*)d_in[5];
    const float* bv = (const float*)d_in[6];
    const float* wa = (const float*)d_in[7];
    const float* ba = (const float*)d_in[8];
    const float* gm = (const float*)d_in[9];
    float* y = (float*)d_out;

    cudaFuncSetAttribute(proj_kernel, cudaFuncAttributeMaxDynamicSharedMemorySize, 69632);
    cudaFuncSetAttribute(flash_mma,  cudaFuncAttributeMaxDynamicSharedMemorySize, 104448);
    cudaFuncSetAttribute(out_kernel, cudaFuncAttributeMaxDynamicSharedMemorySize, 84000);

    proj_kernel<<<dim3(N / 64, B), 384, 67584>>>(x, wk, bk, wq, bq, wv, bv);
    flash_mma<<<dim3(N / 128, B), 256, 104448>>>();
    out_kernel<<<dim3(N / 64, B), 256, 82944>>>(x, wa, ba, gm, y);
}

// round 7
// speedup vs baseline: 3.8260x; 1.0748x over previous
#include <cuda_runtime.h>
#include <math.h>
#include <stdint.h>

static constexpr int B = 8, C = 256, E = 64, N = 4096;

__device__ float g_fT[B * N * E];  // key    [b][n][e]
__device__ float g_gT[B * N * E];  // query  [b][n][e]
__device__ float g_hE[B * E * N];  // value  [b][e][n]  (key-contiguous)
__device__ float g_vT[B * N * E];  // attn out [b][n][e]

// ---------------- helpers ----------------
__device__ __forceinline__ uint32_t smem_u32(const void* p) {
    uint32_t a;
    asm("{ .reg .u64 t; cvta.to.shared.u64 t, %1; cvt.u32.u64 %0, t; }" : "=r"(a) : "l"(p));
    return a;
}
__device__ __forceinline__ void cpasync16(uint32_t dst, const void* src) {
    asm volatile("cp.async.cg.shared.global [%0], [%1], 16;" :: "r"(dst), "l"(src));
}
#define CP_COMMIT() asm volatile("cp.async.commit_group;" ::: "memory")
#define CP_WAIT0()  asm volatile("cp.async.wait_group 0;" ::: "memory")

__device__ __forceinline__ uint32_t to_tf32(float v) {
    uint32_t u;
    asm("cvt.rna.tf32.f32 %0, %1;" : "=r"(u) : "f"(v));
    return u;
}
__device__ __forceinline__ float tf32f(float v) {
    return __uint_as_float(to_tf32(v));
}
// D += A(16x8) * B(8x8), tf32 inputs, fp32 accum
__device__ __forceinline__ void mma8(float* d, const uint32_t* a, const uint32_t* b) {
    asm volatile(
        "mma.sync.aligned.m16n8k8.row.col.f32.tf32.tf32.f32 "
        "{%0,%1,%2,%3}, {%4,%5,%6,%7}, {%8,%9}, {%0,%1,%2,%3};"
        : "+f"(d[0]), "+f"(d[1]), "+f"(d[2]), "+f"(d[3])
        : "r"(a[0]), "r"(a[1]), "r"(a[2]), "r"(a[3]), "r"(b[0]), "r"(b[1]));
}

// ---------------------------------------------------------------------------
// Projection GEMM [192,256] x [256, 64-col tile]; 8x4 microtile per thread.
// grid (N/64, B), 384 threads, 67584 B dyn smem, 2 CTAs/SM.  (unchanged)
// ---------------------------------------------------------------------------
__global__ __launch_bounds__(384, 2) void proj_kernel(
    const float* __restrict__ x,
    const float* __restrict__ wk, const float* __restrict__ bk,
    const float* __restrict__ wq, const float* __restrict__ bq,
    const float* __restrict__ wv, const float* __restrict__ bv)
{
    extern __shared__ float psm[];
    float* xs = psm;              // [64 c][68 n]
    float* ws = psm + 64 * 68;    // [64 c][196 r]

    const int b  = blockIdx.y;
    const int n0 = blockIdx.x << 6;
    const int tid = threadIdx.x;
    const float* xb = x + (size_t)b * C * N;
    const int rg = tid >> 4;      // 8-row group (0..23)
    const int cg = tid & 15;      // 4-col group

    float acc[8][4];
    #pragma unroll
    for (int i = 0; i < 8; i++)
        #pragma unroll
        for (int j = 0; j < 4; j++) acc[i][j] = 0.f;

    for (int c0 = 0; c0 < C; c0 += 64) {
        __syncthreads();
        for (int i = tid; i < 1024; i += 384) {
            int c = i >> 4, n4 = (i & 15) << 2;
            *(float4*)&xs[c * 68 + n4] = *(const float4*)&xb[(size_t)(c0 + c) * N + n0 + n4];
        }
        for (int i = tid; i < 12288; i += 384) {
            int r = i >> 6, c = i & 63;
            float v;
            if (r < 64)       v = wk[r * C + c0 + c];
            else if (r < 128) v = wq[(r - 64) * C + c0 + c];
            else              v = wv[(r - 128) * C + c0 + c];
            ws[c * 196 + r] = v;
        }
        __syncthreads();
        #pragma unroll 4
        for (int c = 0; c < 64; ++c) {
            float4 xv = *(float4*)&xs[c * 68 + (cg << 2)];
            const float4* wp = (const float4*)&ws[c * 196 + rg * 8];
            float4 w0 = wp[0], w1 = wp[1];
            float wr[8] = {w0.x, w0.y, w0.z, w0.w, w1.x, w1.y, w1.z, w1.w};
            #pragma unroll
            for (int i = 0; i < 8; i++) {
                acc[i][0] += wr[i] * xv.x; acc[i][1] += wr[i] * xv.y;
                acc[i][2] += wr[i] * xv.z; acc[i][3] += wr[i] * xv.w;
            }
        }
    }
    #pragma unroll
    for (int i = 0; i < 8; i++) {
        int r = rg * 8 + i;
        float bias = (r < 64) ? bk[r] : (r < 128 ? bq[r - 64] : bv[r - 128]);
        #pragma unroll
        for (int j = 0; j < 4; j++) {
            int n = n0 + (cg << 2) + j;
            float v = acc[i][j] * 0.0625f + bias;
            if (r < 64)       g_fT[((size_t)b * N + n) * E + r] = v;
            else if (r < 128) g_gT[((size_t)b * N + n) * E + (r - 64)] = v;
            else              g_hE[((size_t)b * E + (r - 128)) * N + n] = v;
        }
    }
}

// ---------------------------------------------------------------------------
// Flash attention, mma.sync tf32 (1x for S and PV), interleaved smem layouts.
// Interleave: logical index e -> slot 8*(e>>3) + 2*(e&3) + ((e>>2)&1), so the
// (k, k+4) fragment pair is a single LDS.64. Pitch 72 floats (conflict-free).
// CTA: 256 thr = 8 warps x 16 q-rows (BLOCK_M=128), BLOCK_N=64, 64 tiles.
// smem floats: Kint[64][72] Vint[64][72] Ps[128][72] = 73728 B, 2 CTAs/SM.
// ---------------------------------------------------------------------------
static constexpr int KS0 = 0;
static constexpr int VS0 = 4608;
static constexpr int PS0 = 9216;
static constexpr int NT  = N / 64;   // 64 key tiles

// scatter a float4 of logical cols c0..c0+3 into interleaved row
__device__ __forceinline__ void scatter4(float* row, int c0, float4 v) {
    int base = ((c0 >> 3) << 3) + ((c0 >> 2) & 1);
    row[base]     = v.x;
    row[base + 2] = v.y;
    row[base + 4] = v.z;
    row[base + 6] = v.w;
}

__global__ __launch_bounds__(256, 2) void flash_mma()
{
    extern __shared__ float fsm[];
    const int tid = threadIdx.x;
    const int lane = tid & 31, w = tid >> 5;
    const int tig = lane & 3, gid = lane >> 2;   // mma frag coords
    const int b = blockIdx.y, q0 = blockIdx.x << 7;

    const float* Kg = g_fT + (size_t)b * N * E;
    const float* Vg = g_hE + (size_t)b * E * N;
    const float* Qg = g_gT + ((size_t)b * N + q0) * E;

    const int rowf = tid >> 2, cbf = (tid & 3) << 2;  // staging coords

    // stage Q (raw fp32) into Ps, pitch 72
    for (int i = tid; i < 2048; i += 256) {
        int row = i >> 4, c4 = (i & 15) << 2;
        cpasync16(smem_u32(fsm + PS0 + row * 72 + c4), Qg + row * 64 + c4);
    }
    CP_COMMIT();

    // tile 0: K (tf32-rounded) + V (raw) via LDG + scatter STS
    {
        float* krow = fsm + KS0 + rowf * 72;
        float* vrow = fsm + VS0 + rowf * 72;
        #pragma unroll
        for (int i = 0; i < 4; i++) {
            int c0 = cbf + 16 * i;
            float4 kv = *(const float4*)(Kg + (size_t)rowf * 64 + c0);
            float4 vv = *(const float4*)(Vg + (size_t)rowf * N + c0);
            scatter4(krow, c0, make_float4(tf32f(kv.x), tf32f(kv.y), tf32f(kv.z), tf32f(kv.w)));
            scatter4(vrow, c0, vv);
        }
    }
    CP_WAIT0();
    __syncthreads();

    // Q fragments (tf32), register resident: 32 regs
    uint32_t qt[8][4];
    {
        const float* Qs = fsm + PS0 + (w * 16) * 72;
        #pragma unroll
        for (int ks = 0; ks < 8; ks++) {
            int e = tig + 8 * ks;
            qt[ks][0] = to_tf32(Qs[gid * 72 + e]);
            qt[ks][1] = to_tf32(Qs[(gid + 8) * 72 + e]);
            qt[ks][2] = to_tf32(Qs[gid * 72 + e + 4]);
            qt[ks][3] = to_tf32(Qs[(gid + 8) * 72 + e + 4]);
        }
    }
    __syncthreads();   // Ps free for P staging

    float O[8][4];
    #pragma unroll
    for (int j = 0; j < 8; j++)
        #pragma unroll
        for (int i = 0; i < 4; i++) O[j][i] = 0.f;
    float m0 = -1e30f, m1 = -1e30f, l0 = 0.f, l1 = 0.f;

    const int r0 = w * 16 + gid;
    float* rp  = fsm + PS0 + r0 * 72;   // own q-row in Ps
    float* rp8 = rp + 8 * 72;
    const int bse = ((tig & 1) << 2) | (tig >> 1);   // P write slot base

    for (int t = 0; t < NT; ++t) {
        const bool pref = (t < NT - 1);
        const int k0n = (t + 1) << 6;

        // ---- S = qt * K  (single LDS.64 per mma) ----
        float S[8][4];
        #pragma unroll
        for (int j = 0; j < 8; j++)
            #pragma unroll
            for (int i = 0; i < 4; i++) S[j][i] = 0.f;
        {
            const float* Kh = fsm + KS0;
            #pragma unroll
            for (int ks = 0; ks < 8; ks++) {
                int off = 8 * ks + 2 * tig;
                #pragma unroll
                for (int j = 0; j < 8; j++) {
                    float2 kk = *(const float2*)&Kh[(gid + 8 * j) * 72 + off];
                    uint32_t bb[2] = {__float_as_uint(kk.x), __float_as_uint(kk.y)};
                    mma8(S[j], qt[ks], bb);
                }
            }
        }

        // ---- online softmax (rows r0 and r0+8) ----
        float c0m = -1e30f, c1m = -1e30f;
        #pragma unroll
        for (int j = 0; j < 8; j++) {
            c0m = fmaxf(c0m, fmaxf(S[j][0], S[j][1]));
            c1m = fmaxf(c1m, fmaxf(S[j][2], S[j][3]));
        }
        c0m = fmaxf(c0m, __shfl_xor_sync(0xffffffffu, c0m, 1));
        c0m = fmaxf(c0m, __shfl_xor_sync(0xffffffffu, c0m, 2));
        c1m = fmaxf(c1m, __shfl_xor_sync(0xffffffffu, c1m, 1));
        c1m = fmaxf(c1m, __shfl_xor_sync(0xffffffffu, c1m, 2));
        float mn0 = fmaxf(m0, c0m), mn1 = fmaxf(m1, c1m);
        float a0 = __expf(m0 - mn0), a1 = __expf(m1 - mn1);
        m0 = mn0; m1 = mn1;

        float s0 = 0.f, s1 = 0.f;
        #pragma unroll
        for (int j = 0; j < 8; j++) {
            float p00 = __expf(S[j][0] - m0), p01 = __expf(S[j][1] - m0);
            float p10 = __expf(S[j][2] - m1), p11 = __expf(S[j][3] - m1);
            s0 += p00 + p01; s1 += p10 + p11;
            // interleaved P store: keys 8j+2tig, +1 -> slots 8j+bse, +2
            rp [8 * j + bse]     = tf32f(p00);
            rp [8 * j + bse + 2] = tf32f(p01);
            rp8[8 * j + bse]     = tf32f(p10);
            rp8[8 * j + bse + 2] = tf32f(p11);
        }
        s0 += __shfl_xor_sync(0xffffffffu, s0, 1);
        s0 += __shfl_xor_sync(0xffffffffu, s0, 2);
        s1 += __shfl_xor_sync(0xffffffffu, s1, 1);
        s1 += __shfl_xor_sync(0xffffffffu, s1, 2);
        l0 = l0 * a0 + s0;
        l1 = l1 * a1 + s1;
        #pragma unroll
        for (int j = 0; j < 8; j++) {
            O[j][0] *= a0; O[j][1] *= a0; O[j][2] *= a1; O[j][3] *= a1;
        }
        __syncwarp();   // P visible within warp

        // prefetch next K/V tile into registers (hides under PV mma)
        float4 kst[4], vst[4];
        if (pref) {
            #pragma unroll
            for (int i = 0; i < 4; i++) {
                int c0 = cbf + 16 * i;
                kst[i] = *(const float4*)(Kg + (size_t)(k0n + rowf) * 64 + c0);
                vst[i] = *(const float4*)(Vg + (size_t)rowf * N + k0n + c0);
            }
        }

        // ---- O += P V^T ----
        {
            const float* Vs = fsm + VS0;
            #pragma unroll
            for (int ks = 0; ks < 8; ks++) {
                int off = 8 * ks + 2 * tig;
                float2 pA = *(const float2*)&rp[off];    // {pa0, pa2}
                float2 pB = *(const float2*)&rp8[off];   // {pa1, pa3}
                uint32_t pa[4] = {__float_as_uint(pA.x), __float_as_uint(pB.x),
                                  __float_as_uint(pA.y), __float_as_uint(pB.y)};
                #pragma unroll
                for (int j = 0; j < 8; j++) {
                    float2 vv = *(const float2*)&Vs[(gid + 8 * j) * 72 + off];
                    uint32_t vb[2] = {__float_as_uint(vv.x), __float_as_uint(vv.y)};
                    mma8(O[j], pa, vb);
                }
            }
        }

        __syncthreads();   // all warps done reading Kint/Vint

        if (pref) {
            float* krow = fsm + KS0 + rowf * 72;
            float* vrow = fsm + VS0 + rowf * 72;
            #pragma unroll
            for (int i = 0; i < 4; i++) {
                int c0 = cbf + 16 * i;
                scatter4(krow, c0, make_float4(tf32f(kst[i].x), tf32f(kst[i].y),
                                               tf32f(kst[i].z), tf32f(kst[i].w)));
                scatter4(vrow, c0, vst[i]);
            }
        }
        __syncthreads();   // stores visible before next S-phase
    }

    // ---- epilogue: O/l -> Ps -> gmem ----
    {
        float i0 = 1.f / l0, i1 = 1.f / l1;
        #pragma unroll
        for (int j = 0; j < 8; j++) {
            int col = 8 * j + 2 * tig;
            *(float2*)&rp[col]  = make_float2(O[j][0] * i0, O[j][1] * i0);
            *(float2*)&rp8[col] = make_float2(O[j][2] * i1, O[j][3] * i1);
        }
    }
    __syncthreads();
    {
        float* dst = g_vT + ((size_t)b * N + q0) * E;
        for (int i = tid; i < 2048; i += 256) {
            int row = i >> 4, c4 = (i & 15) << 2;
            *(float4*)(dst + (size_t)row * 64 + c4) = *(float4*)(fsm + PS0 + row * 72 + c4);
        }
    }
}

// ---------------------------------------------------------------------------
// Output: y = gamma * (w_att @ v / 8 + b_att) + x   (unchanged, known-good)
// ---------------------------------------------------------------------------
__global__ __launch_bounds__(256) void out_kernel(
    const float* __restrict__ x, const float* __restrict__ w_att,
    const float* __restrict__ b_att, const float* __restrict__ gamma,
    float* __restrict__ y)
{
    extern __shared__ float sm[];
    float* ws = sm;               // [256][64]
    float* as = sm + 256 * 64;    // [64][68]
    int b = blockIdx.y, n0 = blockIdx.x << 6;
    int tid = threadIdx.x;

    float4* ws4 = (float4*)ws;
    const float4* wg4 = (const float4*)w_att;
    for (int idx = tid; idx < 4096; idx += 256) ws4[idx] = wg4[idx];
    const float* src = g_vT + ((size_t)b * N + n0) * E;
    for (int idx = tid; idx < 4096; idx += 256) {
        int nl = idx >> 6, e = idx & 63;
        as[nl * 68 + e] = src[idx];
    }
    __syncthreads();

    int tx = tid & 63, ty = tid >> 6;
    const float* xcol = x + ((size_t)b * C) * N + n0 + tx;
    float* ycol = y + ((size_t)b * C) * N + n0 + tx;
    const float4* a4 = (const float4*)&as[tx * 68];

    for (int m0 = 0; m0 < 64; m0 += 4) {
        float acc[4] = {0.f, 0.f, 0.f, 0.f};
        #pragma unroll
        for (int e4 = 0; e4 < 16; e4++) {
            float4 a = a4[e4];
            #pragma unroll
            for (int mi = 0; mi < 4; mi++) {
                int c = ty + 4 * (m0 + mi);
                float4 wv = ((const float4*)(ws + c * 64))[e4];
                acc[mi] += a.x * wv.x + a.y * wv.y + a.z * wv.z + a.w * wv.w;
            }
        }
        #pragma unroll
        for (int mi = 0; mi < 4; mi++) {
            int c = ty + 4 * (m0 + mi);
            float o = acc[mi] * 0.125f + b_att[c];
            ycol[(size_t)c * N] = gamma[c] * o + xcol[(size_t)c * N];
        }
    }
}

// ---------------------------------------------------------------------------
extern "C" void kernel_launch(void* const* d_in, const int* in_sizes, int n_in,
                              void* d_out, int out_size)
{
    const float* x  = (const float*)d_in[0];
    const float* wk = (const float*)d_in[1];
    const float* bk = (const float*)d_in[2];
    const float* wq = (const float*)d_in[3];
    const float* bq = (const float*)d_in[4];
    const float* wv = (const float*)d_in[5];
    const float* bv = (const float*)d_in[6];
    const float* wa = (const float*)d_in[7];
    const float* ba = (const float*)d_in[8];
    const float* gm = (const float*)d_in[9];
    float* y = (float*)d_out;

    cudaFuncSetAttribute(proj_kernel, cudaFuncAttributeMaxDynamicSharedMemorySize, 69632);
    cudaFuncSetAttribute(flash_mma,  cudaFuncAttributeMaxDynamicSharedMemorySize, 73728);
    cudaFuncSetAttribute(out_kernel, cudaFuncAttributeMaxDynamicSharedMemorySize, 84000);

    proj_kernel<<<dim3(N / 64, B), 384, 67584>>>(x, wk, bk, wq, bq, wv, bv);
    flash_mma<<<dim3(N / 128, B), 256, 73728>>>();
    out_kernel<<<dim3(N / 64, B), 256, 82944>>>(x, wa, ba, gm, y);
}

// round 8
// speedup vs baseline: 4.2739x; 1.1171x over previous
#include <cuda_runtime.h>
#include <math.h>
#include <stdint.h>

static constexpr int B = 8, C = 256, E = 64, N = 4096;

__device__ float g_fT[B * N * E];  // key    [b][n][e]
__device__ float g_gT[B * N * E];  // query  [b][n][e]
__device__ float g_hE[B * E * N];  // value  [b][e][n]  (key-contiguous)
__device__ float g_vT[B * N * E];  // attn out [b][n][e]

// ---------------- helpers ----------------
__device__ __forceinline__ uint32_t smem_u32(const void* p) {
    uint32_t a;
    asm("{ .reg .u64 t; cvta.to.shared.u64 t, %1; cvt.u32.u64 %0, t; }" : "=r"(a) : "l"(p));
    return a;
}
__device__ __forceinline__ void cpasync16(uint32_t dst, const void* src) {
    asm volatile("cp.async.cg.shared.global [%0], [%1], 16;" :: "r"(dst), "l"(src));
}
#define CP_COMMIT() asm volatile("cp.async.commit_group;" ::: "memory")
#define CP_WAIT0()  asm volatile("cp.async.wait_group 0;" ::: "memory")

__device__ __forceinline__ uint32_t to_tf32(float v) {
    uint32_t u;
    asm("cvt.rna.tf32.f32 %0, %1;" : "=r"(u) : "f"(v));
    return u;
}
__device__ __forceinline__ float tf32f(float v) {
    return __uint_as_float(to_tf32(v));
}
// D += A(16x8) * B(8x8), tf32 inputs, fp32 accum
__device__ __forceinline__ void mma8(float* d, const uint32_t* a, const uint32_t* b) {
    asm volatile(
        "mma.sync.aligned.m16n8k8.row.col.f32.tf32.tf32.f32 "
        "{%0,%1,%2,%3}, {%4,%5,%6,%7}, {%8,%9}, {%0,%1,%2,%3};"
        : "+f"(d[0]), "+f"(d[1]), "+f"(d[2]), "+f"(d[3])
        : "r"(a[0]), "r"(a[1]), "r"(a[2]), "r"(a[3]), "r"(b[0]), "r"(b[1]));
}

// ---------------------------------------------------------------------------
// Projection GEMM [192,256] x [256, 64-col tile]; 8x4 microtile per thread.
// grid (N/64, B), 384 threads, 67584 B dyn smem, 2 CTAs/SM.  (unchanged)
// ---------------------------------------------------------------------------
__global__ __launch_bounds__(384, 2) void proj_kernel(
    const float* __restrict__ x,
    const float* __restrict__ wk, const float* __restrict__ bk,
    const float* __restrict__ wq, const float* __restrict__ bq,
    const float* __restrict__ wv, const float* __restrict__ bv)
{
    extern __shared__ float psm[];
    float* xs = psm;              // [64 c][68 n]
    float* ws = psm + 64 * 68;    // [64 c][196 r]

    const int b  = blockIdx.y;
    const int n0 = blockIdx.x << 6;
    const int tid = threadIdx.x;
    const float* xb = x + (size_t)b * C * N;
    const int rg = tid >> 4;      // 8-row group (0..23)
    const int cg = tid & 15;      // 4-col group

    float acc[8][4];
    #pragma unroll
    for (int i = 0; i < 8; i++)
        #pragma unroll
        for (int j = 0; j < 4; j++) acc[i][j] = 0.f;

    for (int c0 = 0; c0 < C; c0 += 64) {
        __syncthreads();
        for (int i = tid; i < 1024; i += 384) {
            int c = i >> 4, n4 = (i & 15) << 2;
            *(float4*)&xs[c * 68 + n4] = *(const float4*)&xb[(size_t)(c0 + c) * N + n0 + n4];
        }
        for (int i = tid; i < 12288; i += 384) {
            int r = i >> 6, c = i & 63;
            float v;
            if (r < 64)       v = wk[r * C + c0 + c];
            else if (r < 128) v = wq[(r - 64) * C + c0 + c];
            else              v = wv[(r - 128) * C + c0 + c];
            ws[c * 196 + r] = v;
        }
        __syncthreads();
        #pragma unroll 4
        for (int c = 0; c < 64; ++c) {
            float4 xv = *(float4*)&xs[c * 68 + (cg << 2)];
            const float4* wp = (const float4*)&ws[c * 196 + rg * 8];
            float4 w0 = wp[0], w1 = wp[1];
            float wr[8] = {w0.x, w0.y, w0.z, w0.w, w1.x, w1.y, w1.z, w1.w};
            #pragma unroll
            for (int i = 0; i < 8; i++) {
                acc[i][0] += wr[i] * xv.x; acc[i][1] += wr[i] * xv.y;
                acc[i][2] += wr[i] * xv.z; acc[i][3] += wr[i] * xv.w;
            }
        }
    }
    #pragma unroll
    for (int i = 0; i < 8; i++) {
        int r = rg * 8 + i;
        float bias = (r < 64) ? bk[r] : (r < 128 ? bq[r - 64] : bv[r - 128]);
        #pragma unroll
        for (int j = 0; j < 4; j++) {
            int n = n0 + (cg << 2) + j;
            float v = acc[i][j] * 0.0625f + bias;
            if (r < 64)       g_fT[((size_t)b * N + n) * E + r] = v;
            else if (r < 128) g_gT[((size_t)b * N + n) * E + (r - 64)] = v;
            else              g_hE[((size_t)b * E + (r - 128)) * N + n] = v;
        }
    }
}

// ---------------------------------------------------------------------------
// Flash attention, mma.sync tf32. K interleaved (pitch 72, LDS.64 frags),
// V raw (pitch 68, scalar frags — conflict-free). K+V double-buffered,
// ONE barrier per tile, lazy O-rescale via warp vote.
// CTA: 256 thr = 8 warps x 16 q-rows (BLOCK_M=128), BLOCK_N=64, 64 tiles.
// smem floats: K 2x[64][72], V 2x[64][68], Ps [128][72] = 108544 B, 2 CTAs/SM.
// ---------------------------------------------------------------------------
static constexpr int KS0 = 0;        // K: buffer b at KS0 + b*4608
static constexpr int VS0 = 9216;     // V: buffer b at VS0 + b*4352
static constexpr int PS0 = 17920;    // Ps [128][72]
static constexpr int NT  = N / 64;   // 64 key tiles

// scatter a float4 of logical cols c0..c0+3 into interleaved row (pitch 72)
__device__ __forceinline__ void scatter4(float* row, int c0, float4 v) {
    int base = ((c0 >> 3) << 3) + ((c0 >> 2) & 1);
    row[base]     = v.x;
    row[base + 2] = v.y;
    row[base + 4] = v.z;
    row[base + 6] = v.w;
}

__global__ __launch_bounds__(256, 2) void flash_mma()
{
    extern __shared__ float fsm[];
    const int tid = threadIdx.x;
    const int lane = tid & 31, w = tid >> 5;
    const int tig = lane & 3, gid = lane >> 2;   // mma frag coords
    const int b = blockIdx.y, q0 = blockIdx.x << 7;

    const float* Kg = g_fT + (size_t)b * N * E;
    const float* Vg = g_hE + (size_t)b * E * N;
    const float* Qg = g_gT + ((size_t)b * N + q0) * E;

    const int rowf = tid >> 2, cbf = (tid & 3) << 2;  // staging coords

    // stage Q (raw fp32) into Ps, pitch 72
    for (int i = tid; i < 2048; i += 256) {
        int row = i >> 4, c4 = (i & 15) << 2;
        cpasync16(smem_u32(fsm + PS0 + row * 72 + c4), Qg + row * 64 + c4);
    }
    // V tile 0 (raw) via cp.async into buffer 0
    for (int i = tid; i < 1024; i += 256) {
        int row = i >> 4, c4 = (i & 15) << 2;
        cpasync16(smem_u32(fsm + VS0 + row * 68 + c4), Vg + (size_t)row * N + c4);
    }
    CP_COMMIT();

    // K tile 0 (tf32-rounded) via LDG + scatter into buffer 0
    {
        float* krow = fsm + KS0 + rowf * 72;
        #pragma unroll
        for (int i = 0; i < 4; i++) {
            int c0 = cbf + 16 * i;
            float4 kv = *(const float4*)(Kg + (size_t)rowf * 64 + c0);
            scatter4(krow, c0, make_float4(tf32f(kv.x), tf32f(kv.y), tf32f(kv.z), tf32f(kv.w)));
        }
    }
    CP_WAIT0();
    __syncthreads();

    // Q fragments (tf32), register resident: 32 regs
    uint32_t qt[8][4];
    {
        const float* Qs = fsm + PS0 + (w * 16) * 72;
        #pragma unroll
        for (int ks = 0; ks < 8; ks++) {
            int e = tig + 8 * ks;
            qt[ks][0] = to_tf32(Qs[gid * 72 + e]);
            qt[ks][1] = to_tf32(Qs[(gid + 8) * 72 + e]);
            qt[ks][2] = to_tf32(Qs[gid * 72 + e + 4]);
            qt[ks][3] = to_tf32(Qs[(gid + 8) * 72 + e + 4]);
        }
    }
    __syncthreads();   // Ps free for P staging

    float O[8][4];
    #pragma unroll
    for (int j = 0; j < 8; j++)
        #pragma unroll
        for (int i = 0; i < 4; i++) O[j][i] = 0.f;
    float m0 = -1e30f, m1 = -1e30f, l0 = 0.f, l1 = 0.f;

    const int r0 = w * 16 + gid;
    float* rp  = fsm + PS0 + r0 * 72;   // own q-row in Ps
    float* rp8 = rp + 8 * 72;
    const int bse = ((tig & 1) << 2) | (tig >> 1);   // P write slot base

    for (int t = 0; t < NT; ++t) {
        const int buf = t & 1, nb = buf ^ 1;
        const bool pref = (t < NT - 1);
        const int k0n = (t + 1) << 6;

        // async V prefetch for next tile (other buffer)
        if (pref) {
            #pragma unroll
            for (int i = 0; i < 4; i++)
                cpasync16(smem_u32(fsm + VS0 + nb * 4352 + rowf * 68 + cbf + 16 * i),
                          Vg + (size_t)rowf * N + k0n + cbf + 16 * i);
            CP_COMMIT();
        }

        // ---- S = qt * K  (interleaved, single LDS.64 per mma) ----
        float S[8][4];
        #pragma unroll
        for (int j = 0; j < 8; j++)
            #pragma unroll
            for (int i = 0; i < 4; i++) S[j][i] = 0.f;
        {
            const float* Kh = fsm + KS0 + buf * 4608;
            #pragma unroll
            for (int ks = 0; ks < 8; ks++) {
                int off = 8 * ks + 2 * tig;
                #pragma unroll
                for (int j = 0; j < 8; j++) {
                    float2 kk = *(const float2*)&Kh[(gid + 8 * j) * 72 + off];
                    uint32_t bb[2] = {__float_as_uint(kk.x), __float_as_uint(kk.y)};
                    mma8(S[j], qt[ks], bb);
                }
            }
        }

        // ---- online softmax (rows r0 and r0+8) ----
        float c0m = -1e30f, c1m = -1e30f;
        #pragma unroll
        for (int j = 0; j < 8; j++) {
            c0m = fmaxf(c0m, fmaxf(S[j][0], S[j][1]));
            c1m = fmaxf(c1m, fmaxf(S[j][2], S[j][3]));
        }
        c0m = fmaxf(c0m, __shfl_xor_sync(0xffffffffu, c0m, 1));
        c0m = fmaxf(c0m, __shfl_xor_sync(0xffffffffu, c0m, 2));
        c1m = fmaxf(c1m, __shfl_xor_sync(0xffffffffu, c1m, 1));
        c1m = fmaxf(c1m, __shfl_xor_sync(0xffffffffu, c1m, 2));
        float mn0 = fmaxf(m0, c0m), mn1 = fmaxf(m1, c1m);
        bool need = (mn0 > m0) || (mn1 > m1);
        float a0 = __expf(m0 - mn0), a1 = __expf(m1 - mn1);
        m0 = mn0; m1 = mn1;

        float s0 = 0.f, s1 = 0.f;
        #pragma unroll
        for (int j = 0; j < 8; j++) {
            float p00 = __expf(S[j][0] - m0), p01 = __expf(S[j][1] - m0);
            float p10 = __expf(S[j][2] - m1), p11 = __expf(S[j][3] - m1);
            s0 += p00 + p01; s1 += p10 + p11;
            rp [8 * j + bse]     = tf32f(p00);
            rp [8 * j + bse + 2] = tf32f(p01);
            rp8[8 * j + bse]     = tf32f(p10);
            rp8[8 * j + bse + 2] = tf32f(p11);
        }
        s0 += __shfl_xor_sync(0xffffffffu, s0, 1);
        s0 += __shfl_xor_sync(0xffffffffu, s0, 2);
        s1 += __shfl_xor_sync(0xffffffffu, s1, 1);
        s1 += __shfl_xor_sync(0xffffffffu, s1, 2);
        l0 = l0 * a0 + s0;
        l1 = l1 * a1 + s1;
        if (__any_sync(0xffffffffu, need)) {   // lazy rescale
            #pragma unroll
            for (int j = 0; j < 8; j++) {
                O[j][0] *= a0; O[j][1] *= a0; O[j][2] *= a1; O[j][3] *= a1;
            }
        }
        __syncwarp();   // P visible within warp

        // K prefetch into registers (hides under PV mma)
        float4 kst[4];
        if (pref) {
            #pragma unroll
            for (int i = 0; i < 4; i++)
                kst[i] = *(const float4*)(Kg + (size_t)(k0n + rowf) * 64 + cbf + 16 * i);
        }

        // ---- O += P V^T  (V raw pitch 68, conflict-free scalar frags) ----
        {
            const float* Vs = fsm + VS0 + buf * 4352;
            #pragma unroll
            for (int ks = 0; ks < 8; ks++) {
                int off = 8 * ks + 2 * tig;
                float2 pA = *(const float2*)&rp[off];    // {pa0, pa2}
                float2 pB = *(const float2*)&rp8[off];   // {pa1, pa3}
                uint32_t pa[4] = {__float_as_uint(pA.x), __float_as_uint(pB.x),
                                  __float_as_uint(pA.y), __float_as_uint(pB.y)};
                int k = tig + 8 * ks;
                #pragma unroll
                for (int j = 0; j < 8; j++) {
                    const float* vr = &Vs[(gid + 8 * j) * 68 + k];
                    uint32_t vb[2] = {__float_as_uint(vr[0]), __float_as_uint(vr[4])};
                    mma8(O[j], pa, vb);
                }
            }
        }

        // scatter next K tile into other buffer (reads of nb ended last tile)
        if (pref) {
            float* krow = fsm + KS0 + nb * 4608 + rowf * 72;
            #pragma unroll
            for (int i = 0; i < 4; i++) {
                int c0 = cbf + 16 * i;
                scatter4(krow, c0, make_float4(tf32f(kst[i].x), tf32f(kst[i].y),
                                               tf32f(kst[i].z), tf32f(kst[i].w)));
            }
        }
        CP_WAIT0();
        __syncthreads();   // single barrier per tile
    }

    // ---- epilogue: O/l -> Ps -> gmem ----
    {
        float i0 = 1.f / l0, i1 = 1.f / l1;
        #pragma unroll
        for (int j = 0; j < 8; j++) {
            int col = 8 * j + 2 * tig;
            *(float2*)&rp[col]  = make_float2(O[j][0] * i0, O[j][1] * i0);
            *(float2*)&rp8[col] = make_float2(O[j][2] * i1, O[j][3] * i1);
        }
    }
    __syncthreads();
    {
        float* dst = g_vT + ((size_t)b * N + q0) * E;
        for (int i = tid; i < 2048; i += 256) {
            int row = i >> 4, c4 = (i & 15) << 2;
            *(float4*)(dst + (size_t)row * 64 + c4) = *(float4*)(fsm + PS0 + row * 72 + c4);
        }
    }
}

// ---------------------------------------------------------------------------
// Output: y = gamma * (w_att @ v / 8 + b_att) + x   (unchanged, known-good)
// ---------------------------------------------------------------------------
__global__ __launch_bounds__(256) void out_kernel(
    const float* __restrict__ x, const float* __restrict__ w_att,
    const float* __restrict__ b_att, const float* __restrict__ gamma,
    float* __restrict__ y)
{
    extern __shared__ float sm[];
    float* ws = sm;               // [256][64]
    float* as = sm + 256 * 64;    // [64][68]
    int b = blockIdx.y, n0 = blockIdx.x << 6;
    int tid = threadIdx.x;

    float4* ws4 = (float4*)ws;
    const float4* wg4 = (const float4*)w_att;
    for (int idx = tid; idx < 4096; idx += 256) ws4[idx] = wg4[idx];
    const float* src = g_vT + ((size_t)b * N + n0) * E;
    for (int idx = tid; idx < 4096; idx += 256) {
        int nl = idx >> 6, e = idx & 63;
        as[nl * 68 + e] = src[idx];
    }
    __syncthreads();

    int tx = tid & 63, ty = tid >> 6;
    const float* xcol = x + ((size_t)b * C) * N + n0 + tx;
    float* ycol = y + ((size_t)b * C) * N + n0 + tx;
    const float4* a4 = (const float4*)&as[tx * 68];

    for (int m0 = 0; m0 < 64; m0 += 4) {
        float acc[4] = {0.f, 0.f, 0.f, 0.f};
        #pragma unroll
        for (int e4 = 0; e4 < 16; e4++) {
            float4 a = a4[e4];
            #pragma unroll
            for (int mi = 0; mi < 4; mi++) {
                int c = ty + 4 * (m0 + mi);
                float4 wv = ((const float4*)(ws + c * 64))[e4];
                acc[mi] += a.x * wv.x + a.y * wv.y + a.z * wv.z + a.w * wv.w;
            }
        }
        #pragma unroll
        for (int mi = 0; mi < 4; mi++) {
            int c = ty + 4 * (m0 + mi);
            float o = acc[mi] * 0.125f + b_att[c];
            ycol[(size_t)c * N] = gamma[c] * o + xcol[(size_t)c * N];
        }
    }
}

// ---------------------------------------------------------------------------
extern "C" void kernel_launch(void* const* d_in, const int* in_sizes, int n_in,
                              void* d_out, int out_size)
{
    const float* x  = (const float*)d_in[0];
    const float* wk = (const float*)d_in[1];
    const float* bk = (const float*)d_in[2];
    const float* wq = (const float*)d_in[3];
    const float* bq = (const float*)d_in[4];
    const float* wv = (const float*)d_in[5];
    const float* bv = (const float*)d_in[6];
    const float* wa = (const float*)d_in[7];
    const float* ba = (const float*)d_in[8];
    const float* gm = (const float*)d_in[9];
    float* y = (float*)d_out;

    cudaFuncSetAttribute(proj_kernel, cudaFuncAttributeMaxDynamicSharedMemorySize, 69632);
    cudaFuncSetAttribute(flash_mma,  cudaFuncAttributeMaxDynamicSharedMemorySize, 108544);
    cudaFuncSetAttribute(out_kernel, cudaFuncAttributeMaxDynamicSharedMemorySize, 84000);

    proj_kernel<<<dim3(N / 64, B), 384, 67584>>>(x, wk, bk, wq, bq, wv, bv);
    flash_mma<<<dim3(N / 128, B), 256, 108544>>>();
    out_kernel<<<dim3(N / 64, B), 256, 82944>>>(x, wa, ba, gm, y);
}